// round 12
// baseline (speedup 1.0000x reference)
#include <cuda_runtime.h>
#include <cuda_bf16.h>
#include <math.h>

#define VOCAB   128
#define HIDDEN  1024
#define BATCH   64
#define SEQ     512

#define RSTRIDE 520    // reduce-buffer k-block stride (floats)
#define LOGITS_ELEMS (BATCH*SEQ*VOCAB)
// smem: Wsm[1024*32] + Hsm[16*1024] + Red[8*RSTRIDE] + embWsm[128*32]
#define SCAN_SMEM  ((1024*32 + 16*1024 + 8*RSTRIDE + 128*32) * 4)   // 229632 bytes
#define SCAN_THREADS 512

// ---------------- device scratch ----------------
__device__ float    g_hs[(size_t)SEQ * BATCH * HIDDEN];  // all h_t (128 MB)
__device__ unsigned g_bar[128];                          // group g counter at [g*32]: 1 line each

// ---------------- packed f32x2 helpers ----------------
typedef unsigned long long u64;

__device__ __forceinline__ u64 pack2(float x, float y) {
    u64 r;
    asm("mov.b64 %0, {%1, %2};" : "=l"(r) : "r"(__float_as_uint(x)), "r"(__float_as_uint(y)));
    return r;
}
__device__ __forceinline__ void unpack2(u64 v, float& x, float& y) {
    unsigned a, b;
    asm("mov.b64 {%0, %1}, %2;" : "=r"(a), "=r"(b) : "l"(v));
    x = __uint_as_float(a); y = __uint_as_float(b);
}
__device__ __forceinline__ void fma2(u64& acc, u64 a, u64 b) {
    asm("fma.rn.f32x2 %0, %1, %2, %0;" : "+l"(acc) : "l"(a), "l"(b));
}
__device__ __forceinline__ void add2(u64& acc, u64 v) {
    asm("add.rn.f32x2 %0, %0, %1;" : "+l"(acc) : "l"(v));
}
__device__ __forceinline__ unsigned ld_acquire(const unsigned* p) {
    unsigned v;
    asm volatile("ld.acquire.gpu.global.u32 %0, [%1];" : "=r"(v) : "l"(p) : "memory");
    return v;
}

// ================================================================================
// k-loop: warp = (kq, rh); lane = (rq = lane>>3 -> rows r0, r0+1; ng = lane&7).
// Covers k in [kq*128, +128) for 2 rows x 4 cols. acc[2][2] = 8 registers.
// Hsm: plain float4 slots H4[row*256 + (k>>2)]. Every h-load phase is a pure
// broadcast (8 lanes same row) -> conflict-free without swizzle.
// ================================================================================
__device__ __forceinline__ void kloop_512(const float* __restrict__ Wsm,
                                          const float4* __restrict__ H4,
                                          int kbase, int r0, int ng, u64 acc[2][2])
{
    const int slot0 = kbase >> 2;
    #pragma unroll 4
    for (int cc = 0; cc < 32; ++cc) {        // 32 chunks of 4 k
        const int kl = kbase + cc * 4;
        longlong2 wv0 = *(const longlong2*)&Wsm[(kl + 0) * 32 + ng * 4];
        longlong2 wv1 = *(const longlong2*)&Wsm[(kl + 1) * 32 + ng * 4];
        longlong2 wv2 = *(const longlong2*)&Wsm[(kl + 2) * 32 + ng * 4];
        longlong2 wv3 = *(const longlong2*)&Wsm[(kl + 3) * 32 + ng * 4];
        const int hs = slot0 + cc;
        #pragma unroll
        for (int r = 0; r < 2; ++r) {
            float4 h4 = H4[(r0 + r) * 256 + hs];
            u64 ha = pack2(h4.x, h4.x);
            u64 hb = pack2(h4.y, h4.y);
            u64 hc = pack2(h4.z, h4.z);
            u64 hd = pack2(h4.w, h4.w);
            fma2(acc[r][0], ha, (u64)wv0.x);  fma2(acc[r][1], ha, (u64)wv0.y);
            fma2(acc[r][0], hb, (u64)wv1.x);  fma2(acc[r][1], hb, (u64)wv1.y);
            fma2(acc[r][0], hc, (u64)wv2.x);  fma2(acc[r][1], hc, (u64)wv2.y);
            fma2(acc[r][0], hd, (u64)wv3.x);  fma2(acc[r][1], hd, (u64)wv3.y);
        }
    }
}

// Warp (kq, rh) stages rows rh*8..+8 over slots [kq*32, +32). Per lane 8 float4.
// Only this warp reads these slots -> __syncwarp suffices.
__device__ __forceinline__ void stage_own_slice(float4* __restrict__ H4,
                                                const float* __restrict__ src,
                                                int row0, int kc_l)
{
    float4 v[8];
    #pragma unroll
    for (int j = 0; j < 8; ++j)
        v[j] = *(const float4*)&src[(size_t)(row0 + j) * 1024 + kc_l * 4];
    #pragma unroll
    for (int j = 0; j < 8; ++j)
        H4[(row0 + j) * 256 + kc_l] = v[j];
    __syncwarp();
}

// ================================================================================
// Kernel 1: persistent RNN scan (single launch, t in [0, SEQ)).
// 128 CTAs = 4 batch-groups x 32 col-slices, 512 threads (16 warps = 8 k-blocks
// x 2 row-halves -> 4 warps/SMSP for latency coverage). Round-7 barrier.
// ================================================================================
__global__ void __launch_bounds__(SCAN_THREADS, 1)
rnn_scan_kernel(const int*   __restrict__ x,
                const float* __restrict__ h0,
                const float* __restrict__ emb,
                const float* __restrict__ W_hx,
                const float* __restrict__ b_hx,
                const float* __restrict__ W_hh,
                float*       __restrict__ d_out,
                int out_size)
{
    extern __shared__ float smem[];
    float*  Wsm    = smem;                       // [1024][32]
    float*  Hsm    = smem + 1024 * 32;           // [16][1024] plain float4 slots
    float4* H4     = (float4*)Hsm;
    float*  Red    = Hsm + 16 * 1024;            // [8][RSTRIDE]
    float*  embWsm = Red + 8 * RSTRIDE;          // [128][32]
    __shared__ volatile int sflag;

    const int tid = threadIdx.x;
    const int cta = blockIdx.x;
    const int gb  = cta >> 5;          // batch group 0..3
    const int gn  = cta & 31;          // column slice 0..31
    const int b0  = gb * 16;
    const int n0  = gn * 32;

    if (tid == 0) sflag = -1;

    const int lane  = tid & 31;
    const int w     = tid >> 5;        // 0..15
    const int kq    = w >> 1;          // k-block 0..7
    const int rh    = w & 1;           // row-half 0..1
    const int rq    = lane >> 3;       // row-pair 0..3
    const int ng    = lane & 7;        // col-quad 0..7
    const int kbase = kq * 128;
    const int r0    = rh * 8 + rq * 2; // first of this lane's 2 rows
    const int row0s = rh * 8;          // staging row base
    const int kc_l  = kq * 32 + lane;  // staging slot
    const int orow  = tid >> 5;        // output row 0..15 (one col per thread)
    const int ocol  = tid & 31;        // output col 0..31

    // ---------------- Prologue: embWsm = emb @ W_hx[:, n0:+32] + b_hx ----------------
    for (int i = tid; i < 1024 * 8; i += SCAN_THREADS) {
        int k = i >> 3, q = i & 7;
        *(float4*)&Wsm[k * 32 + q * 4] =
            *(const float4*)&W_hx[(size_t)k * 1024 + n0 + q * 4];
    }
    __syncthreads();
    for (int vg = 0; vg < 8; ++vg) {
        stage_own_slice(H4, &emb[(size_t)(vg * 16) * 1024], row0s, kc_l);
        float bb = b_hx[n0 + ocol];
        u64 acc[2][2];
        acc[0][0] = acc[0][1] = acc[1][0] = acc[1][1] = 0ull;
        kloop_512(Wsm, H4, kbase, r0, ng, acc);
        #pragma unroll
        for (int r = 0; r < 2; ++r) {
            *(u64*)&Red[kq * RSTRIDE + (r0 + r) * 32 + ng * 4]     = acc[r][0];
            *(u64*)&Red[kq * RSTRIDE + (r0 + r) * 32 + ng * 4 + 2] = acc[r][1];
        }
        __syncthreads();
        float s = Red[tid];
        #pragma unroll
        for (int kk = 1; kk < 8; ++kk) s += Red[kk * RSTRIDE + tid];
        embWsm[(vg * 16 + orow) * 32 + ocol] = s + bb;
        __syncthreads();   // Red reads done before next vg's writes
    }

    // Load W_hh slice (overwrites Wsm).
    for (int i = tid; i < 1024 * 8; i += SCAN_THREADS) {
        int k = i >> 3, q = i & 7;
        *(float4*)&Wsm[k * 32 + q * 4] =
            *(const float4*)&W_hh[(size_t)k * 1024 + n0 + q * 4];
    }
    __syncthreads();

    // ---------------- Scan ----------------
    unsigned* gbar = &g_bar[gb * 32];   // one 128B line per group

    for (int t = 0; t < SEQ; ++t) {
        if (t > 0) {
            if (tid == 0) {
                unsigned tgt = 32u * (unsigned)t;
                while (ld_acquire(gbar) < tgt) { }
                sflag = t;
            }
            while (sflag < t) { }       // cheap SMEM spin
        }

        const float* hsrc = (t == 0)
            ? (h0 + (size_t)b0 * 1024)
            : (g_hs + (size_t)(t - 1) * (BATCH * HIDDEN) + (size_t)b0 * 1024);
        stage_own_slice(H4, hsrc, row0s, kc_l);

        int   myx = x[(size_t)(b0 + orow) * SEQ + t];   // early issue
        float e   = embWsm[myx * 32 + ocol];

        u64 acc[2][2];
        acc[0][0] = acc[0][1] = acc[1][0] = acc[1][1] = 0ull;
        kloop_512(Wsm, H4, kbase, r0, ng, acc);

        #pragma unroll
        for (int r = 0; r < 2; ++r) {
            *(u64*)&Red[kq * RSTRIDE + (r0 + r) * 32 + ng * 4]     = acc[r][0];
            *(u64*)&Red[kq * RSTRIDE + (r0 + r) * 32 + ng * 4 + 2] = acc[r][1];
        }
        __syncthreads();                     // sync A: Red writes -> reduce reads

        float s = Red[tid];
        #pragma unroll
        for (int kk = 1; kk < 8; ++kk) s += Red[kk * RSTRIDE + tid];
        float hv = tanhf(s + e);
        g_hs[(size_t)t * (BATCH * HIDDEN) + (size_t)(b0 + orow) * 1024 + n0 + ocol] = hv;
        if (t == SEQ - 1 && out_size >= LOGITS_ELEMS + BATCH * HIDDEN)
            d_out[(size_t)LOGITS_ELEMS + (size_t)(b0 + orow) * 1024 + n0 + ocol] = hv;

        __syncthreads();                     // sync B: all h stores HB tid0's release
        if (tid == 0) {
            __threadfence();
            atomicAdd(gbar, 1u);
        }
    }
}

// ================================================================================
// Kernel 2: logits. TWO timesteps per CTA, 8x8 thread tile (round-7 config).
// Also resets the scan counters for the NEXT invocation (runs last).
// ================================================================================
#define ASTRIDE 20

__global__ void __launch_bounds__(256)
logits_kernel(const float* __restrict__ W_out,
              const float* __restrict__ b_out,
              float*       __restrict__ out)
{
    __shared__ float Asm[128 * ASTRIDE];
    __shared__ float Wsm[16 * 128];

    const int tid = threadIdx.x;
    if (blockIdx.x == 0 && tid < 128) g_bar[tid] = 0u;   // reset for next replay

    const int rg  = tid >> 4;
    const int cg  = tid & 15;

    u64 acc[8][4];
    #pragma unroll
    for (int i = 0; i < 8; ++i)
        #pragma unroll
        for (int j = 0; j < 4; ++j) acc[i][j] = 0ull;

    const float* A = g_hs + (size_t)blockIdx.x * 2 * (BATCH * HIDDEN);
    const int ar = tid >> 1;
    const int ac = (tid & 1) * 8;

    for (int k0 = 0; k0 < 1024; k0 += 16) {
        __syncthreads();
        {
            float4 a0 = *(const float4*)&A[(size_t)ar * 1024 + k0 + ac];
            float4 a1 = *(const float4*)&A[(size_t)ar * 1024 + k0 + ac + 4];
            *(float4*)&Asm[ar * ASTRIDE + ac]     = a0;
            *(float4*)&Asm[ar * ASTRIDE + ac + 4] = a1;
        }
        {
            const float* src = &W_out[(size_t)(k0 + rg) * 128 + cg * 8];
            *(float4*)&Wsm[rg * 128 + cg * 8]     = *(const float4*)&src[0];
            *(float4*)&Wsm[rg * 128 + cg * 8 + 4] = *(const float4*)&src[4];
        }
        __syncthreads();
        #pragma unroll
        for (int kk = 0; kk < 16; ++kk) {
            const float* wrow = &Wsm[kk * 128 + cg * 8];
            u64 w0 = *(const u64*)&wrow[0];
            u64 w1 = *(const u64*)&wrow[2];
            u64 w2 = *(const u64*)&wrow[4];
            u64 w3 = *(const u64*)&wrow[6];
            #pragma unroll
            for (int i = 0; i < 8; ++i) {
                float a = Asm[(rg * 8 + i) * ASTRIDE + kk];
                u64 aa = pack2(a, a);
                fma2(acc[i][0], aa, w0);
                fma2(acc[i][1], aa, w1);
                fma2(acc[i][2], aa, w2);
                fma2(acc[i][3], aa, w3);
            }
        }
    }

    float4 bv0 = *(const float4*)&b_out[cg * 8];
    float4 bv1 = *(const float4*)&b_out[cg * 8 + 4];
    #pragma unroll
    for (int i = 0; i < 8; ++i) {
        int row = rg * 8 + i;
        int t   = blockIdx.x * 2 + (row >> 6);
        int b   = row & 63;
        float r0, r1, r2, r3, r4, r5, r6, r7;
        unpack2(acc[i][0], r0, r1);
        unpack2(acc[i][1], r2, r3);
        unpack2(acc[i][2], r4, r5);
        unpack2(acc[i][3], r6, r7);
        float* dst = &out[(size_t)b * (SEQ * VOCAB) + (size_t)t * VOCAB + cg * 8];
        *(float4*)dst       = make_float4(r0 + bv0.x, r1 + bv0.y, r2 + bv0.z, r3 + bv0.w);
        *(float4*)(dst + 4) = make_float4(r4 + bv1.x, r5 + bv1.y, r6 + bv1.z, r7 + bv1.w);
    }
}

// ================================================================================
extern "C" void kernel_launch(void* const* d_in, const int* in_sizes, int n_in,
                              void* d_out, int out_size)
{
    const int*   x     = (const int*)  d_in[0];
    const float* h     = (const float*)d_in[1];
    const float* emb   = (const float*)d_in[2];
    const float* W_hx  = (const float*)d_in[3];
    const float* b_hx  = (const float*)d_in[4];
    const float* W_hh  = (const float*)d_in[5];
    const float* W_out = (const float*)d_in[6];
    const float* b_out = (const float*)d_in[7];
    float*       out   = (float*)d_out;
    (void)in_sizes; (void)n_in;

    cudaFuncSetAttribute(rnn_scan_kernel,
                         cudaFuncAttributeMaxDynamicSharedMemorySize, SCAN_SMEM);

    rnn_scan_kernel<<<128, SCAN_THREADS, SCAN_SMEM>>>(x, h, emb, W_hx, b_hx, W_hh,
                                                      out, out_size);
    logits_kernel<<<SEQ/2, 256>>>(W_out, b_out, out);
}

// round 13
// speedup vs baseline: 1.4736x; 1.4736x over previous
#include <cuda_runtime.h>
#include <cuda_bf16.h>
#include <math.h>

#define VOCAB   128
#define HIDDEN  1024
#define BATCH   64
#define SEQ     512

#define RSTRIDE 520    // reduce-buffer warp stride (floats, 8B aligned)
#define LOGITS_ELEMS (BATCH*SEQ*VOCAB)
// smem: Wsm[1024*32] + Hsm[16*1024] + Red[8*RSTRIDE] + embWsm[128*32]
#define SCAN_SMEM  ((1024*32 + 16*1024 + 8*RSTRIDE + 128*32) * 4)   // 229632 bytes

// ---------------- device scratch ----------------
__device__ float    g_hs[(size_t)SEQ * BATCH * HIDDEN];  // all h_t (128 MB)
__device__ unsigned g_bar[128];                          // group g counter at [g*32]: 1 line each

// ---------------- packed f32x2 helpers ----------------
typedef unsigned long long u64;

__device__ __forceinline__ u64 pack2(float x, float y) {
    u64 r;
    asm("mov.b64 %0, {%1, %2};" : "=l"(r) : "r"(__float_as_uint(x)), "r"(__float_as_uint(y)));
    return r;
}
__device__ __forceinline__ void unpack2(u64 v, float& x, float& y) {
    unsigned a, b;
    asm("mov.b64 {%0, %1}, %2;" : "=r"(a), "=r"(b) : "l"(v));
    x = __uint_as_float(a); y = __uint_as_float(b);
}
__device__ __forceinline__ void fma2(u64& acc, u64 a, u64 b) {
    asm("fma.rn.f32x2 %0, %1, %2, %0;" : "+l"(acc) : "l"(a), "l"(b));
}
__device__ __forceinline__ void add2(u64& acc, u64 v) {
    asm("add.rn.f32x2 %0, %0, %1;" : "+l"(acc) : "l"(v));
}
__device__ __forceinline__ unsigned ld_acquire(const unsigned* p) {
    unsigned v;
    asm volatile("ld.acquire.gpu.global.u32 %0, [%1];" : "=r"(v) : "l"(p) : "memory");
    return v;
}

// ================================================================================
// Round-7 k-loop: lane = (bg = lane>>3, ng = lane&7); warp w covers k in
// [w*128, +128), lane computes 4 rows (bg*4..+4) x 4 cols (ng*4..+4).
// Hsm layout: float4 slot (row*256 + ((k>>2) ^ bg_of_row)), bg_of_row = row>>2
// -> 16B-aligned float4 h loads, conflict-free across the warp's 4 bg groups.
// ================================================================================
__device__ __forceinline__ void kloop_partial(const float* __restrict__ Wsm,
                                              const float4* __restrict__ H4,
                                              int kbase, int bg, int ng, u64 acc[4][2])
{
    #pragma unroll 4
    for (int k = kbase; k < kbase + 128; k += 4) {
        const int kc = k >> 2;
        longlong2 wv0 = *(const longlong2*)&Wsm[(k + 0) * 32 + ng * 4];
        longlong2 wv1 = *(const longlong2*)&Wsm[(k + 1) * 32 + ng * 4];
        longlong2 wv2 = *(const longlong2*)&Wsm[(k + 2) * 32 + ng * 4];
        longlong2 wv3 = *(const longlong2*)&Wsm[(k + 3) * 32 + ng * 4];
        #pragma unroll
        for (int i = 0; i < 4; ++i) {
            float4 h4 = H4[(bg * 4 + i) * 256 + (kc ^ bg)];
            u64 ha = pack2(h4.x, h4.x);
            u64 hb = pack2(h4.y, h4.y);
            u64 hc = pack2(h4.z, h4.z);
            u64 hd = pack2(h4.w, h4.w);
            fma2(acc[i][0], ha, (u64)wv0.x);  fma2(acc[i][1], ha, (u64)wv0.y);
            fma2(acc[i][0], hb, (u64)wv1.x);  fma2(acc[i][1], hb, (u64)wv1.y);
            fma2(acc[i][0], hc, (u64)wv2.x);  fma2(acc[i][1], hc, (u64)wv2.y);
            fma2(acc[i][0], hd, (u64)wv3.x);  fma2(acc[i][1], hd, (u64)wv3.y);
        }
    }
}

// Per-warp staging of this warp's own k-slice: rows 0..15, cols [w*128, +128).
// Only this warp ever reads these slots -> __syncwarp suffices.
__device__ __forceinline__ void stage_own_slice(float4* __restrict__ H4,
                                                const float* __restrict__ src,
                                                int kc_l /* = w*32 + lane */)
{
    float4 v[16];
    #pragma unroll
    for (int j = 0; j < 16; ++j)
        v[j] = *(const float4*)&src[(size_t)j * 1024 + kc_l * 4];
    #pragma unroll
    for (int j = 0; j < 16; ++j)
        H4[j * 256 + (kc_l ^ (j >> 2))] = v[j];
    __syncwarp();
}

// ================================================================================
// Kernel 1: persistent RNN scan, single launch, t in [0, SEQ).
// 128 CTAs = 4 batch-groups x 32 col-slices. Round-7 barrier (padded counter,
// tid0 poll + SMEM flag, fence + atomicAdd). Round-7 k-loop.
// ================================================================================
__global__ void __launch_bounds__(256, 1)
rnn_scan_kernel(const int*   __restrict__ x,
                const float* __restrict__ h0,
                const float* __restrict__ emb,
                const float* __restrict__ W_hx,
                const float* __restrict__ b_hx,
                const float* __restrict__ W_hh,
                float*       __restrict__ d_out,
                int out_size)
{
    extern __shared__ float smem[];
    float*  Wsm    = smem;                       // [1024][32]
    float*  Hsm    = smem + 1024 * 32;           // [16][1024] swizzled float4
    float4* H4     = (float4*)Hsm;
    float*  Red    = Hsm + 16 * 1024;            // [8][RSTRIDE]
    float*  embWsm = Red + 8 * RSTRIDE;          // [128][32]
    __shared__ volatile int sflag;

    const int tid = threadIdx.x;
    const int cta = blockIdx.x;
    const int gb  = cta >> 5;          // batch group 0..3
    const int gn  = cta & 31;          // column slice 0..31
    const int b0  = gb * 16;
    const int n0  = gn * 32;

    if (tid == 0) sflag = -1;

    const int lane  = tid & 31;
    const int w     = tid >> 5;
    const int bg    = lane >> 3;
    const int ng    = lane & 7;
    const int kbase = w * 128;
    const int kc_l  = w * 32 + lane;
    const int o2    = tid * 2;
    const int rb    = o2 >> 5;         // batch row within group (0..15)
    const int rn    = o2 & 31;         // even col within slice

    // ---------------- Prologue: embWsm = emb @ W_hx[:, n0:+32] + b_hx ----------------
    for (int i = tid; i < 1024 * 8; i += 256) {
        int k = i >> 3, q = i & 7;
        *(float4*)&Wsm[k * 32 + q * 4] =
            *(const float4*)&W_hx[(size_t)k * 1024 + n0 + q * 4];
    }
    __syncthreads();
    for (int vg = 0; vg < 8; ++vg) {
        stage_own_slice(H4, &emb[(size_t)(vg * 16) * 1024], kc_l);
        float2 bb = *(const float2*)&b_hx[n0 + rn];
        u64 acc[4][2];
        #pragma unroll
        for (int i = 0; i < 4; ++i) { acc[i][0] = 0ull; acc[i][1] = 0ull; }
        kloop_partial(Wsm, H4, kbase, bg, ng, acc);
        #pragma unroll
        for (int i = 0; i < 4; ++i) {
            int o = (bg * 4 + i) * 32 + ng * 4;
            *(u64*)&Red[w * RSTRIDE + o]     = acc[i][0];
            *(u64*)&Red[w * RSTRIDE + o + 2] = acc[i][1];
        }
        __syncthreads();
        u64 s = *(const u64*)&Red[o2];
        #pragma unroll
        for (int ww = 1; ww < 8; ++ww)
            add2(s, *(const u64*)&Red[ww * RSTRIDE + o2]);
        float s0, s1;
        unpack2(s, s0, s1);
        *(float2*)&embWsm[(vg * 16 + rb) * 32 + rn] =
            make_float2(s0 + bb.x, s1 + bb.y);
        __syncthreads();   // Red reads done before next vg's writes
    }

    // Load W_hh slice (overwrites Wsm; prologue reads are sync'd above).
    for (int i = tid; i < 1024 * 8; i += 256) {
        int k = i >> 3, q = i & 7;
        *(float4*)&Wsm[k * 32 + q * 4] =
            *(const float4*)&W_hh[(size_t)k * 1024 + n0 + q * 4];
    }
    __syncthreads();

    // ---------------- Scan ----------------
    unsigned* gbar = &g_bar[gb * 32];   // one 128B line per group

    for (int t = 0; t < SEQ; ++t) {
        if (t > 0) {
            if (tid == 0) {
                unsigned tgt = 32u * (unsigned)t;
                while (ld_acquire(gbar) < tgt) { }
                sflag = t;
            }
            while (sflag < t) { }       // cheap SMEM spin
        }

        const float* hsrc = (t == 0)
            ? (h0 + (size_t)b0 * 1024)
            : (g_hs + (size_t)(t - 1) * (BATCH * HIDDEN) + (size_t)b0 * 1024);
        stage_own_slice(H4, hsrc, kc_l);

        int myx = x[(size_t)(b0 + rb) * SEQ + t];   // early issue; used post-kloop
        float2 e = *(const float2*)&embWsm[myx * 32 + rn];

        u64 acc[4][2];
        #pragma unroll
        for (int i = 0; i < 4; ++i) { acc[i][0] = 0ull; acc[i][1] = 0ull; }
        kloop_partial(Wsm, H4, kbase, bg, ng, acc);

        #pragma unroll
        for (int i = 0; i < 4; ++i) {
            int o = (bg * 4 + i) * 32 + ng * 4;
            *(u64*)&Red[w * RSTRIDE + o]     = acc[i][0];
            *(u64*)&Red[w * RSTRIDE + o + 2] = acc[i][1];
        }
        __syncthreads();                     // sync A: Red writes -> reduce reads

        u64 s = *(const u64*)&Red[o2];
        #pragma unroll
        for (int ww = 1; ww < 8; ++ww)
            add2(s, *(const u64*)&Red[ww * RSTRIDE + o2]);
        float s0, s1;
        unpack2(s, s0, s1);
        float r0 = tanhf(s0 + e.x);
        float r1 = tanhf(s1 + e.y);
        *(float2*)&g_hs[(size_t)t * (BATCH * HIDDEN) + (size_t)(b0 + rb) * 1024 + n0 + rn]
            = make_float2(r0, r1);
        if (t == SEQ - 1 && out_size >= LOGITS_ELEMS + BATCH * HIDDEN) {
            *(float2*)&d_out[(size_t)LOGITS_ELEMS + (size_t)(b0 + rb) * 1024 + n0 + rn]
                = make_float2(r0, r1);
        }

        __syncthreads();                     // sync B: all h stores HB tid0's release
        if (tid == 0) {
            __threadfence();
            atomicAdd(gbar, 1u);
        }
    }
}

// ================================================================================
// Kernel 2: logits. TWO timesteps per CTA, 8x8 thread tile, 2 CTAs/SM
// (grid 256 <= 2*148 -> single wave; sync bubbles overlap across CTAs).
// Also resets the scan counters for the NEXT invocation (runs last).
// ================================================================================
#define ASTRIDE 20

__global__ void __launch_bounds__(256, 2)
logits_kernel(const float* __restrict__ W_out,
              const float* __restrict__ b_out,
              float*       __restrict__ out)
{
    __shared__ float Asm[128 * ASTRIDE];
    __shared__ float Wsm[16 * 128];

    const int tid = threadIdx.x;
    if (blockIdx.x == 0 && tid < 128) g_bar[tid] = 0u;   // reset for next replay

    const int rg  = tid >> 4;
    const int cg  = tid & 15;

    u64 acc[8][4];
    #pragma unroll
    for (int i = 0; i < 8; ++i)
        #pragma unroll
        for (int j = 0; j < 4; ++j) acc[i][j] = 0ull;

    const float* A = g_hs + (size_t)blockIdx.x * 2 * (BATCH * HIDDEN);
    const int ar = tid >> 1;
    const int ac = (tid & 1) * 8;

    for (int k0 = 0; k0 < 1024; k0 += 16) {
        __syncthreads();
        {
            float4 a0 = *(const float4*)&A[(size_t)ar * 1024 + k0 + ac];
            float4 a1 = *(const float4*)&A[(size_t)ar * 1024 + k0 + ac + 4];
            *(float4*)&Asm[ar * ASTRIDE + ac]     = a0;
            *(float4*)&Asm[ar * ASTRIDE + ac + 4] = a1;
        }
        {
            const float* src = &W_out[(size_t)(k0 + rg) * 128 + cg * 8];
            *(float4*)&Wsm[rg * 128 + cg * 8]     = *(const float4*)&src[0];
            *(float4*)&Wsm[rg * 128 + cg * 8 + 4] = *(const float4*)&src[4];
        }
        __syncthreads();
        #pragma unroll
        for (int kk = 0; kk < 16; ++kk) {
            const float* wrow = &Wsm[kk * 128 + cg * 8];
            u64 w0 = *(const u64*)&wrow[0];
            u64 w1 = *(const u64*)&wrow[2];
            u64 w2 = *(const u64*)&wrow[4];
            u64 w3 = *(const u64*)&wrow[6];
            #pragma unroll
            for (int i = 0; i < 8; ++i) {
                float a = Asm[(rg * 8 + i) * ASTRIDE + kk];
                u64 aa = pack2(a, a);
                fma2(acc[i][0], aa, w0);
                fma2(acc[i][1], aa, w1);
                fma2(acc[i][2], aa, w2);
                fma2(acc[i][3], aa, w3);
            }
        }
    }

    float4 bv0 = *(const float4*)&b_out[cg * 8];
    float4 bv1 = *(const float4*)&b_out[cg * 8 + 4];
    #pragma unroll
    for (int i = 0; i < 8; ++i) {
        int row = rg * 8 + i;
        int t   = blockIdx.x * 2 + (row >> 6);
        int b   = row & 63;
        float r0, r1, r2, r3, r4, r5, r6, r7;
        unpack2(acc[i][0], r0, r1);
        unpack2(acc[i][1], r2, r3);
        unpack2(acc[i][2], r4, r5);
        unpack2(acc[i][3], r6, r7);
        float* dst = &out[(size_t)b * (SEQ * VOCAB) + (size_t)t * VOCAB + cg * 8];
        *(float4*)dst       = make_float4(r0 + bv0.x, r1 + bv0.y, r2 + bv0.z, r3 + bv0.w);
        *(float4*)(dst + 4) = make_float4(r4 + bv1.x, r5 + bv1.y, r6 + bv1.z, r7 + bv1.w);
    }
}

// ================================================================================
extern "C" void kernel_launch(void* const* d_in, const int* in_sizes, int n_in,
                              void* d_out, int out_size)
{
    const int*   x     = (const int*)  d_in[0];
    const float* h     = (const float*)d_in[1];
    const float* emb   = (const float*)d_in[2];
    const float* W_hx  = (const float*)d_in[3];
    const float* b_hx  = (const float*)d_in[4];
    const float* W_hh  = (const float*)d_in[5];
    const float* W_out = (const float*)d_in[6];
    const float* b_out = (const float*)d_in[7];
    float*       out   = (float*)d_out;
    (void)in_sizes; (void)n_in;

    cudaFuncSetAttribute(rnn_scan_kernel,
                         cudaFuncAttributeMaxDynamicSharedMemorySize, SCAN_SMEM);

    rnn_scan_kernel<<<128, 256, SCAN_SMEM>>>(x, h, emb, W_hx, b_hx, W_hh,
                                             out, out_size);
    logits_kernel<<<SEQ/2, 256>>>(W_out, b_out, out);
}